// round 9
// baseline (speedup 1.0000x reference)
#include <cuda_runtime.h>

// GNN: logits = relu( (relu(xW0^T+b0) + norm-scatter) W1^T + b1 ) Wc^T + bc
// Pipeline: gemm1 | zero_cnt, hist, scan, fill (CSR build) | agg (per-node warp) | gemm2.
// GEMM: 128x128 block tile, 512 threads, 4x8 micro-tile, unit-stride rgrp rows
// (conflict-free x loads), f32x2 packed FMA.

#define DIMK 128
#define NCLS 4
#define BM   128
#define XS_P 132
#define MAXN 100000
#define MAXE 800000

__device__ __align__(16) float g_h0[(size_t)MAXN * DIMK];
__device__ __align__(16) float g_agg[(size_t)MAXN * DIMK];   // pre-normalized agg
__device__ int g_cnt[MAXN];
__device__ int g_cur[MAXN];
__device__ int g_rptr[MAXN + 1];
__device__ int g_eidx[MAXE];

typedef unsigned long long u64;

__device__ __forceinline__ u64 pk2(float lo, float hi) {
    u64 r; asm("mov.b64 %0, {%1, %2};" : "=l"(r) : "f"(lo), "f"(hi)); return r;
}
__device__ __forceinline__ u64 fma2(u64 a, u64 b, u64 c) {
    u64 d; asm("fma.rn.f32x2 %0, %1, %2, %3;" : "=l"(d) : "l"(a), "l"(b), "l"(c)); return d;
}
__device__ __forceinline__ float2 upk2(u64 v) {
    float lo, hi; asm("mov.b64 {%0, %1}, %2;" : "=f"(lo), "=f"(hi) : "l"(v));
    float2 f; f.x = lo; f.y = hi; return f;
}

// ---------------------------------------------------------------------------
// GEMM1: h0 = relu(x @ W0^T + b0).
// ---------------------------------------------------------------------------
extern "C" __global__ __launch_bounds__(512)
void k_gemm1(const float* __restrict__ x, const float* __restrict__ W0,
             const float* __restrict__ b0, int n)
{
    extern __shared__ float smem[];
    float* Ws = smem;                 // [128 k][128 c]
    float* xs = smem + DIMK * DIMK;   // [128 r][132]
    const int tid  = threadIdx.x;
    const int row0 = blockIdx.x * BM;

#pragma unroll
    for (int it = 0; it < 8; ++it) {
        int idx = tid + it * 512;     // 0..4095 float4 units
        int j   = idx & 127;
        int k4  = (idx >> 7) * 4;
        float4 w = *(const float4*)&W0[j * DIMK + k4];
        Ws[(k4 + 0) * DIMK + j] = w.x;
        Ws[(k4 + 1) * DIMK + j] = w.y;
        Ws[(k4 + 2) * DIMK + j] = w.z;
        Ws[(k4 + 3) * DIMK + j] = w.w;
    }
#pragma unroll
    for (int it = 0; it < 8; ++it) {
        int idx = tid + it * 512;
        int r   = idx >> 5;
        int c4  = (idx & 31) * 4;
        int grow = row0 + r;
        float4 v = make_float4(0.f, 0.f, 0.f, 0.f);
        if (grow < n) v = *(const float4*)&x[(size_t)grow * DIMK + c4];
        *(float4*)&xs[r * XS_P + c4] = v;
    }
    __syncthreads();

    const int warp = tid >> 5, lane = tid & 31;
    const int warp_m = warp & 3, warp_n = warp >> 2;
    const int rgrp = lane >> 2, cgrp = lane & 3;
    const int r_base = warp_m * 32 + rgrp;       // rows r_base + i*8
    const int c_base = warp_n * 32 + cgrp * 8;

    u64 acc[4][4];
#pragma unroll
    for (int i = 0; i < 4; ++i)
#pragma unroll
        for (int u = 0; u < 4; ++u) acc[i][u] = 0ull;

#pragma unroll 4
    for (int k = 0; k < DIMK; ++k) {
        const float* wsk = &Ws[k * DIMK];
        ulonglong2 wa = *(const ulonglong2*)&wsk[c_base];
        ulonglong2 wb = *(const ulonglong2*)&wsk[c_base + 4];
#pragma unroll
        for (int i = 0; i < 4; ++i) {
            float xv = xs[(r_base + i * 8) * XS_P + k];
            u64 x0 = pk2(xv, xv);
            acc[i][0] = fma2(x0, wa.x, acc[i][0]);
            acc[i][1] = fma2(x0, wa.y, acc[i][1]);
            acc[i][2] = fma2(x0, wb.x, acc[i][2]);
            acc[i][3] = fma2(x0, wb.y, acc[i][3]);
        }
    }

    float4 ba = *(const float4*)&b0[c_base];
    float4 bb = *(const float4*)&b0[c_base + 4];
#pragma unroll
    for (int i = 0; i < 4; ++i) {
        int grow = row0 + r_base + i * 8;
        if (grow < n) {
            float2 p0 = upk2(acc[i][0]), p1 = upk2(acc[i][1]);
            float2 p2 = upk2(acc[i][2]), p3 = upk2(acc[i][3]);
            float4 oa, ob;
            oa.x = fmaxf(p0.x + ba.x, 0.f); oa.y = fmaxf(p0.y + ba.y, 0.f);
            oa.z = fmaxf(p1.x + ba.z, 0.f); oa.w = fmaxf(p1.y + ba.w, 0.f);
            ob.x = fmaxf(p2.x + bb.x, 0.f); ob.y = fmaxf(p2.y + bb.y, 0.f);
            ob.z = fmaxf(p3.x + bb.z, 0.f); ob.w = fmaxf(p3.y + bb.w, 0.f);
            *(float4*)&g_h0[(size_t)grow * DIMK + c_base]     = oa;
            *(float4*)&g_h0[(size_t)grow * DIMK + c_base + 4] = ob;
        }
    }
}

// ---------------------------------------------------------------------------
// CSR build: zero counts, histogram over dst, exclusive scan, fill src list.
// ---------------------------------------------------------------------------
extern "C" __global__ void k_zero(int n)
{
    int i = blockIdx.x * blockDim.x + threadIdx.x;
    if (i < n) g_cnt[i] = 0;
}

extern "C" __global__ void k_hist(const int* __restrict__ ei, int nE)
{
    int e = blockIdx.x * blockDim.x + threadIdx.x;
    if (e < nE) atomicAdd(&g_cnt[ei[e]], 1);
}

extern "C" __global__ __launch_bounds__(1024)
void k_scan(int n)
{
    __shared__ int ssum[1024];
    const int t  = threadIdx.x;
    const int CH = (MAXN + 1023) / 1024;   // 98
    const int base = t * CH;

    int s = 0;
    for (int j = 0; j < CH; ++j) {
        int idx = base + j;
        if (idx < n) s += g_cnt[idx];
    }
    ssum[t] = s;
    __syncthreads();
    // Hillis-Steele inclusive scan over 1024 partials.
    for (int off = 1; off < 1024; off <<= 1) {
        int v = 0;
        if (t >= off) v = ssum[t - off];
        __syncthreads();
        if (t >= off) ssum[t] += v;
        __syncthreads();
    }
    int run = ssum[t] - s;                 // exclusive prefix for this chunk
    for (int j = 0; j < CH; ++j) {
        int idx = base + j;
        if (idx < n) {
            g_rptr[idx] = run;
            g_cur[idx]  = run;
            run += g_cnt[idx];
        }
    }
    if (t == 1023) g_rptr[n] = ssum[1023];
}

extern "C" __global__ void k_fill(const int* __restrict__ ei, int nE)
{
    int e = blockIdx.x * blockDim.x + threadIdx.x;
    if (e < nE) {
        int dst = ei[e];
        int src = ei[nE + e];
        int pos = atomicAdd(&g_cur[dst], 1);
        g_eidx[pos] = src;
    }
}

// ---------------------------------------------------------------------------
// Aggregation: one warp per node. acc = sum h0[src]; agg = acc/max(deg,1).
// ---------------------------------------------------------------------------
extern "C" __global__ __launch_bounds__(256)
void k_agg(int n)
{
    int node = blockIdx.x * 8 + (threadIdx.x >> 5);
    int lane = threadIdx.x & 31;
    if (node >= n) return;
    int beg = g_rptr[node], end = g_rptr[node + 1];
    float4 acc = make_float4(0.f, 0.f, 0.f, 0.f);
    for (int e = beg; e < end; ++e) {
        int src = g_eidx[e];
        float4 v = *(const float4*)&g_h0[(size_t)src * DIMK + lane * 4];
        acc.x += v.x; acc.y += v.y; acc.z += v.z; acc.w += v.w;
    }
    float inv = (end > beg) ? 1.0f / (float)(end - beg) : 0.0f;
    acc.x *= inv; acc.y *= inv; acc.z *= inv; acc.w *= inv;
    *(float4*)&g_agg[(size_t)node * DIMK + lane * 4] = acc;
}

// ---------------------------------------------------------------------------
// GEMM2 fused: hin = h0 + agg (pre-normalized); h = relu(hin@W1^T + b1);
// logits = h@Wc^T + bc (classifier reduced via shfl + smem atomics).
// ---------------------------------------------------------------------------
extern "C" __global__ __launch_bounds__(512)
void k_gemm2(const float* __restrict__ W1, const float* __restrict__ b1,
             const float* __restrict__ Wc, const float* __restrict__ bc,
             float* __restrict__ out, int n)
{
    extern __shared__ float smem[];
    float* Ws  = smem;                       // 128*128
    float* xs  = smem + DIMK * DIMK;         // 128*132
    float* Wcs = xs + BM * XS_P;             // 4*128
    float* red = Wcs + NCLS * DIMK;          // 128*4
    const int tid  = threadIdx.x;
    const int row0 = blockIdx.x * BM;

#pragma unroll
    for (int it = 0; it < 8; ++it) {
        int idx = tid + it * 512;
        int j   = idx & 127;
        int k4  = (idx >> 7) * 4;
        float4 w = *(const float4*)&W1[j * DIMK + k4];
        Ws[(k4 + 0) * DIMK + j] = w.x;
        Ws[(k4 + 1) * DIMK + j] = w.y;
        Ws[(k4 + 2) * DIMK + j] = w.z;
        Ws[(k4 + 3) * DIMK + j] = w.w;
    }
    if (tid < 128) {
        float4 w = *(const float4*)&Wc[tid * 4];
        *(float4*)&Wcs[tid * 4] = w;
    }
    if (tid < BM * NCLS) red[tid] = bc[tid & 3];

    // hin tile: h0 + agg (already normalized)
#pragma unroll
    for (int it = 0; it < 8; ++it) {
        int idx = tid + it * 512;
        int r   = idx >> 5;
        int c4  = (idx & 31) * 4;
        int grow = row0 + r;
        float4 v = make_float4(0.f, 0.f, 0.f, 0.f);
        if (grow < n) {
            float4 hv = *(const float4*)&g_h0[(size_t)grow * DIMK + c4];
            float4 av = *(const float4*)&g_agg[(size_t)grow * DIMK + c4];
            v.x = hv.x + av.x;
            v.y = hv.y + av.y;
            v.z = hv.z + av.z;
            v.w = hv.w + av.w;
        }
        *(float4*)&xs[r * XS_P + c4] = v;
    }
    __syncthreads();

    const int warp = tid >> 5, lane = tid & 31;
    const int warp_m = warp & 3, warp_n = warp >> 2;
    const int rgrp = lane >> 2, cgrp = lane & 3;
    const int r_base = warp_m * 32 + rgrp;
    const int c_base = warp_n * 32 + cgrp * 8;

    u64 acc[4][4];
#pragma unroll
    for (int i = 0; i < 4; ++i)
#pragma unroll
        for (int u = 0; u < 4; ++u) acc[i][u] = 0ull;

#pragma unroll 4
    for (int k = 0; k < DIMK; ++k) {
        const float* wsk = &Ws[k * DIMK];
        ulonglong2 wa = *(const ulonglong2*)&wsk[c_base];
        ulonglong2 wb = *(const ulonglong2*)&wsk[c_base + 4];
#pragma unroll
        for (int i = 0; i < 4; ++i) {
            float xv = xs[(r_base + i * 8) * XS_P + k];
            u64 x0 = pk2(xv, xv);
            acc[i][0] = fma2(x0, wa.x, acc[i][0]);
            acc[i][1] = fma2(x0, wa.y, acc[i][1]);
            acc[i][2] = fma2(x0, wb.x, acc[i][2]);
            acc[i][3] = fma2(x0, wb.y, acc[i][3]);
        }
    }

    float4 ba = *(const float4*)&b1[c_base];
    float4 bb = *(const float4*)&b1[c_base + 4];

    float part[4][NCLS];
#pragma unroll
    for (int i = 0; i < 4; ++i) {
        float h[8];
        float2 p0 = upk2(acc[i][0]), p1 = upk2(acc[i][1]);
        float2 p2 = upk2(acc[i][2]), p3 = upk2(acc[i][3]);
        h[0] = fmaxf(p0.x + ba.x, 0.f); h[1] = fmaxf(p0.y + ba.y, 0.f);
        h[2] = fmaxf(p1.x + ba.z, 0.f); h[3] = fmaxf(p1.y + ba.w, 0.f);
        h[4] = fmaxf(p2.x + bb.x, 0.f); h[5] = fmaxf(p2.y + bb.y, 0.f);
        h[6] = fmaxf(p3.x + bb.z, 0.f); h[7] = fmaxf(p3.y + bb.w, 0.f);
#pragma unroll
        for (int c = 0; c < NCLS; ++c) {
            const float* wrow = &Wcs[c * DIMK];
            float s = 0.f;
#pragma unroll
            for (int u = 0; u < 8; ++u) s += h[u] * wrow[c_base + u];
            part[i][c] = s;
        }
    }
#pragma unroll
    for (int i = 0; i < 4; ++i)
#pragma unroll
        for (int c = 0; c < NCLS; ++c) {
            float v = part[i][c];
            v += __shfl_xor_sync(0xffffffffu, v, 1);
            v += __shfl_xor_sync(0xffffffffu, v, 2);
            part[i][c] = v;
        }
    if (cgrp == 0) {
#pragma unroll
        for (int i = 0; i < 4; ++i) {
            int r = r_base + i * 8;
#pragma unroll
            for (int c = 0; c < NCLS; ++c)
                atomicAdd(&red[r * NCLS + c], part[i][c]);
        }
    }
    __syncthreads();
    if (tid < BM) {
        int grow = row0 + tid;
        if (grow < n) {
            float4 o = *(const float4*)&red[tid * NCLS];
            *(float4*)&out[(size_t)grow * NCLS] = o;
        }
    }
}

extern "C" void kernel_launch(void* const* d_in, const int* in_sizes, int n_in,
                              void* d_out, int out_size)
{
    const float* x  = (const float*)d_in[0];
    const int*   ei = (const int*)  d_in[1];
    const float* W0 = (const float*)d_in[2];
    const float* b0 = (const float*)d_in[3];
    const float* W1 = (const float*)d_in[4];
    const float* b1 = (const float*)d_in[5];
    const float* Wc = (const float*)d_in[6];
    const float* bc = (const float*)d_in[7];
    float* out = (float*)d_out;

    int n  = in_sizes[0] / DIMK;     // 100000
    int nE = in_sizes[1] / 2;        // 800000

    int smem1 = (DIMK * DIMK + BM * XS_P) * (int)sizeof(float);
    int smem2 = (DIMK * DIMK + BM * XS_P + NCLS * DIMK + BM * NCLS) * (int)sizeof(float);
    cudaFuncSetAttribute(k_gemm1, cudaFuncAttributeMaxDynamicSharedMemorySize, smem1);
    cudaFuncSetAttribute(k_gemm2, cudaFuncAttributeMaxDynamicSharedMemorySize, smem2);

    int grid = (n + BM - 1) / BM;
    int eblk = (nE + 255) / 256;

    // CSR build (independent of gemm1, serial stream is fine)
    k_zero<<<(n + 255) / 256, 256>>>(n);
    k_hist<<<eblk, 256>>>(ei, nE);
    k_scan<<<1, 1024>>>(n);
    k_fill<<<eblk, 256>>>(ei, nE);

    k_gemm1<<<grid, 512, smem1>>>(x, W0, b0, n);
    k_agg<<<(n + 7) / 8, 256>>>(n);
    k_gemm2<<<grid, 512, smem2>>>(W1, b1, Wc, bc, out, n);
}

// round 12
// speedup vs baseline: 1.2806x; 1.2806x over previous
#include <cuda_runtime.h>

// GNN: logits = relu( (relu(xW0^T+b0) + norm-scatter) W1^T + b1 ) Wc^T + bc
// 3 kernels: gemm1 (+zero agg/deg), edge scatter (vector RED), fused gemm2+classifier.
// GEMM: 128x128 block tile, 512 threads, 4x8 micro-tile with UNIT-STRIDE rgrp rows
// (conflict-free x loads: lane stride 132 = 4 mod 32 banks), f32x2 packed FMA.

#define DIMK 128
#define NCLS 4
#define BM   128
#define XS_P 132
#define MAXN 100000

__device__ __align__(16) float g_h0[(size_t)MAXN * DIMK];
__device__ __align__(16) float g_agg[(size_t)MAXN * DIMK];
__device__ __align__(16) float g_deg[MAXN];

typedef unsigned long long u64;

__device__ __forceinline__ u64 pk2(float lo, float hi) {
    u64 r; asm("mov.b64 %0, {%1, %2};" : "=l"(r) : "f"(lo), "f"(hi)); return r;
}
__device__ __forceinline__ u64 fma2(u64 a, u64 b, u64 c) {
    u64 d; asm("fma.rn.f32x2 %0, %1, %2, %3;" : "=l"(d) : "l"(a), "l"(b), "l"(c)); return d;
}
__device__ __forceinline__ float2 upk2(u64 v) {
    float lo, hi; asm("mov.b64 {%0, %1}, %2;" : "=f"(lo), "=f"(hi) : "l"(v));
    float2 f; f.x = lo; f.y = hi; return f;
}

// ---------------------------------------------------------------------------
// GEMM1: h0 = relu(x @ W0^T + b0). Also zeroes agg/deg rows for this block.
// ---------------------------------------------------------------------------
extern "C" __global__ __launch_bounds__(512)
void k_gemm1(const float* __restrict__ x, const float* __restrict__ W0,
             const float* __restrict__ b0, int n)
{
    extern __shared__ float smem[];
    float* Ws = smem;                 // [128 k][128 c]
    float* xs = smem + DIMK * DIMK;   // [128 r][132]
    const int tid  = threadIdx.x;
    const int row0 = blockIdx.x * BM;

    // Transpose W0 -> Ws[k][c]. Consecutive lanes -> consecutive c: conflict-free.
#pragma unroll
    for (int it = 0; it < 8; ++it) {
        int idx = tid + it * 512;     // 0..4095 float4 units
        int j   = idx & 127;          // output col c
        int k4  = (idx >> 7) * 4;
        float4 w = *(const float4*)&W0[j * DIMK + k4];
        Ws[(k4 + 0) * DIMK + j] = w.x;
        Ws[(k4 + 1) * DIMK + j] = w.y;
        Ws[(k4 + 2) * DIMK + j] = w.z;
        Ws[(k4 + 3) * DIMK + j] = w.w;
    }
    // x tile row-major (pitch 132) + zero agg rows.
#pragma unroll
    for (int it = 0; it < 8; ++it) {
        int idx = tid + it * 512;     // float4 units, 0..4095
        int r   = idx >> 5;
        int c4  = (idx & 31) * 4;
        int grow = row0 + r;
        float4 v = make_float4(0.f, 0.f, 0.f, 0.f);
        if (grow < n) {
            v = *(const float4*)&x[(size_t)grow * DIMK + c4];
            *(float4*)&g_agg[(size_t)grow * DIMK + c4] = make_float4(0.f, 0.f, 0.f, 0.f);
        }
        *(float4*)&xs[r * XS_P + c4] = v;
    }
    if (tid < BM && row0 + tid < n) g_deg[row0 + tid] = 0.f;
    __syncthreads();

    const int warp = tid >> 5, lane = tid & 31;
    const int warp_m = warp & 3, warp_n = warp >> 2;
    const int rgrp = lane >> 2, cgrp = lane & 3;
    const int r_base = warp_m * 32 + rgrp;       // rows r_base + i*8, i=0..3
    const int c_base = warp_n * 32 + cgrp * 8;

    u64 acc[4][4];
#pragma unroll
    for (int i = 0; i < 4; ++i)
#pragma unroll
        for (int u = 0; u < 4; ++u) acc[i][u] = 0ull;

#pragma unroll 4
    for (int k = 0; k < DIMK; ++k) {
        const float* wsk = &Ws[k * DIMK];
        ulonglong2 wa = *(const ulonglong2*)&wsk[c_base];
        ulonglong2 wb = *(const ulonglong2*)&wsk[c_base + 4];
#pragma unroll
        for (int i = 0; i < 4; ++i) {
            float xv = xs[(r_base + i * 8) * XS_P + k];
            u64 x0 = pk2(xv, xv);
            acc[i][0] = fma2(x0, wa.x, acc[i][0]);
            acc[i][1] = fma2(x0, wa.y, acc[i][1]);
            acc[i][2] = fma2(x0, wb.x, acc[i][2]);
            acc[i][3] = fma2(x0, wb.y, acc[i][3]);
        }
    }

    float4 ba = *(const float4*)&b0[c_base];
    float4 bb = *(const float4*)&b0[c_base + 4];
#pragma unroll
    for (int i = 0; i < 4; ++i) {
        int grow = row0 + r_base + i * 8;
        if (grow < n) {
            float2 p0 = upk2(acc[i][0]), p1 = upk2(acc[i][1]);
            float2 p2 = upk2(acc[i][2]), p3 = upk2(acc[i][3]);
            float4 oa, ob;
            oa.x = fmaxf(p0.x + ba.x, 0.f); oa.y = fmaxf(p0.y + ba.y, 0.f);
            oa.z = fmaxf(p1.x + ba.z, 0.f); oa.w = fmaxf(p1.y + ba.w, 0.f);
            ob.x = fmaxf(p2.x + bb.x, 0.f); ob.y = fmaxf(p2.y + bb.y, 0.f);
            ob.z = fmaxf(p3.x + bb.z, 0.f); ob.w = fmaxf(p3.y + bb.w, 0.f);
            *(float4*)&g_h0[(size_t)grow * DIMK + c_base]     = oa;
            *(float4*)&g_h0[(size_t)grow * DIMK + c_base + 4] = ob;
        }
    }
}

// ---------------------------------------------------------------------------
// Scatter: one warp per edge; lane l moves float4 l of the 128-float row.
// ---------------------------------------------------------------------------
extern "C" __global__ void k_scatter(const int* __restrict__ ei, int nE)
{
    int gw   = (int)((blockIdx.x * blockDim.x + threadIdx.x) >> 5);
    int lane = threadIdx.x & 31;
    if (gw >= nE) return;
    int dst = ei[gw];        // edge_index[0][e] -> segment id
    int src = ei[nE + gw];   // edge_index[1][e] -> gathered features
    float4 v = *(const float4*)&g_h0[(size_t)src * DIMK + lane * 4];
    float* p = &g_agg[(size_t)dst * DIMK + lane * 4];
    asm volatile("red.global.add.v4.f32 [%0], {%1,%2,%3,%4};"
                 :: "l"(p), "f"(v.x), "f"(v.y), "f"(v.z), "f"(v.w) : "memory");
    if (lane == 0) atomicAdd(&g_deg[dst], 1.0f);
}

// ---------------------------------------------------------------------------
// GEMM2 fused: hin = h0 + agg/max(deg,1); h = relu(hin@W1^T + b1);
// logits = h@Wc^T + bc (classifier reduced via shfl + smem atomics).
// ---------------------------------------------------------------------------
extern "C" __global__ __launch_bounds__(512)
void k_gemm2(const float* __restrict__ W1, const float* __restrict__ b1,
             const float* __restrict__ Wc, const float* __restrict__ bc,
             float* __restrict__ out, int n)
{
    extern __shared__ float smem[];
    float* Ws  = smem;                       // 128*128
    float* xs  = smem + DIMK * DIMK;         // 128*132
    float* Wcs = xs + BM * XS_P;             // 4*128
    float* red = Wcs + NCLS * DIMK;          // 128*4
    const int tid  = threadIdx.x;
    const int row0 = blockIdx.x * BM;

#pragma unroll
    for (int it = 0; it < 8; ++it) {
        int idx = tid + it * 512;
        int j   = idx & 127;
        int k4  = (idx >> 7) * 4;
        float4 w = *(const float4*)&W1[j * DIMK + k4];
        Ws[(k4 + 0) * DIMK + j] = w.x;
        Ws[(k4 + 1) * DIMK + j] = w.y;
        Ws[(k4 + 2) * DIMK + j] = w.z;
        Ws[(k4 + 3) * DIMK + j] = w.w;
    }
    if (tid < 128) {
        float4 w = *(const float4*)&Wc[tid * 4];
        *(float4*)&Wcs[tid * 4] = w;
    }
    if (tid < BM * NCLS) red[tid] = bc[tid & 3];

    // hin tile: h0 + agg * (1/max(deg,1))
#pragma unroll
    for (int it = 0; it < 8; ++it) {
        int idx = tid + it * 512;
        int r   = idx >> 5;
        int c4  = (idx & 31) * 4;
        int grow = row0 + r;
        float4 v = make_float4(0.f, 0.f, 0.f, 0.f);
        if (grow < n) {
            float4 hv = *(const float4*)&g_h0[(size_t)grow * DIMK + c4];
            float4 av = *(const float4*)&g_agg[(size_t)grow * DIMK + c4];
            float inv = 1.0f / fmaxf(g_deg[grow], 1.0f);
            v.x = hv.x + av.x * inv;
            v.y = hv.y + av.y * inv;
            v.z = hv.z + av.z * inv;
            v.w = hv.w + av.w * inv;
        }
        *(float4*)&xs[r * XS_P + c4] = v;
    }
    __syncthreads();

    const int warp = tid >> 5, lane = tid & 31;
    const int warp_m = warp & 3, warp_n = warp >> 2;
    const int rgrp = lane >> 2, cgrp = lane & 3;
    const int r_base = warp_m * 32 + rgrp;       // rows r_base + i*8
    const int c_base = warp_n * 32 + cgrp * 8;

    u64 acc[4][4];
#pragma unroll
    for (int i = 0; i < 4; ++i)
#pragma unroll
        for (int u = 0; u < 4; ++u) acc[i][u] = 0ull;

#pragma unroll 4
    for (int k = 0; k < DIMK; ++k) {
        const float* wsk = &Ws[k * DIMK];
        ulonglong2 wa = *(const ulonglong2*)&wsk[c_base];
        ulonglong2 wb = *(const ulonglong2*)&wsk[c_base + 4];
#pragma unroll
        for (int i = 0; i < 4; ++i) {
            float xv = xs[(r_base + i * 8) * XS_P + k];
            u64 x0 = pk2(xv, xv);
            acc[i][0] = fma2(x0, wa.x, acc[i][0]);
            acc[i][1] = fma2(x0, wa.y, acc[i][1]);
            acc[i][2] = fma2(x0, wb.x, acc[i][2]);
            acc[i][3] = fma2(x0, wb.y, acc[i][3]);
        }
    }

    float4 ba = *(const float4*)&b1[c_base];
    float4 bb = *(const float4*)&b1[c_base + 4];

    float part[4][NCLS];
#pragma unroll
    for (int i = 0; i < 4; ++i) {
        float h[8];
        float2 p0 = upk2(acc[i][0]), p1 = upk2(acc[i][1]);
        float2 p2 = upk2(acc[i][2]), p3 = upk2(acc[i][3]);
        h[0] = fmaxf(p0.x + ba.x, 0.f); h[1] = fmaxf(p0.y + ba.y, 0.f);
        h[2] = fmaxf(p1.x + ba.z, 0.f); h[3] = fmaxf(p1.y + ba.w, 0.f);
        h[4] = fmaxf(p2.x + bb.x, 0.f); h[5] = fmaxf(p2.y + bb.y, 0.f);
        h[6] = fmaxf(p3.x + bb.z, 0.f); h[7] = fmaxf(p3.y + bb.w, 0.f);
#pragma unroll
        for (int c = 0; c < NCLS; ++c) {
            const float* wrow = &Wcs[c * DIMK];
            float s = 0.f;
#pragma unroll
            for (int u = 0; u < 8; ++u) s += h[u] * wrow[c_base + u];
            part[i][c] = s;
        }
    }
    // Reduce over the 4 cgrp lanes.
#pragma unroll
    for (int i = 0; i < 4; ++i)
#pragma unroll
        for (int c = 0; c < NCLS; ++c) {
            float v = part[i][c];
            v += __shfl_xor_sync(0xffffffffu, v, 1);
            v += __shfl_xor_sync(0xffffffffu, v, 2);
            part[i][c] = v;
        }
    if (cgrp == 0) {
#pragma unroll
        for (int i = 0; i < 4; ++i) {
            int r = r_base + i * 8;
#pragma unroll
            for (int c = 0; c < NCLS; ++c)
                atomicAdd(&red[r * NCLS + c], part[i][c]);
        }
    }
    __syncthreads();
    if (tid < BM) {
        int grow = row0 + tid;
        if (grow < n) {
            float4 o = *(const float4*)&red[tid * NCLS];
            *(float4*)&out[(size_t)grow * NCLS] = o;
        }
    }
}

extern "C" void kernel_launch(void* const* d_in, const int* in_sizes, int n_in,
                              void* d_out, int out_size)
{
    const float* x  = (const float*)d_in[0];
    const int*   ei = (const int*)  d_in[1];
    const float* W0 = (const float*)d_in[2];
    const float* b0 = (const float*)d_in[3];
    const float* W1 = (const float*)d_in[4];
    const float* b1 = (const float*)d_in[5];
    const float* Wc = (const float*)d_in[6];
    const float* bc = (const float*)d_in[7];
    float* out = (float*)d_out;

    int n  = in_sizes[0] / DIMK;     // 100000
    int nE = in_sizes[1] / 2;        // 800000

    int smem1 = (DIMK * DIMK + BM * XS_P) * (int)sizeof(float);
    int smem2 = (DIMK * DIMK + BM * XS_P + NCLS * DIMK + BM * NCLS) * (int)sizeof(float);
    cudaFuncSetAttribute(k_gemm1, cudaFuncAttributeMaxDynamicSharedMemorySize, smem1);
    cudaFuncSetAttribute(k_gemm2, cudaFuncAttributeMaxDynamicSharedMemorySize, smem2);

    int grid = (n + BM - 1) / BM;
    k_gemm1<<<grid, 512, smem1>>>(x, W0, b0, n);

    long long tthreads = (long long)nE * 32;
    int sblocks = (int)((tthreads + 255) / 256);
    k_scatter<<<sblocks, 256>>>(ei, nE);

    k_gemm2<<<grid, 512, smem2>>>(W1, b1, Wc, bc, out, n);
}